// round 1
// baseline (speedup 1.0000x reference)
#include <cuda_runtime.h>
#include <cstdint>

// ---------------- static scratch (no dynamic allocation allowed) ----------------
#define TBITS 21
#define TSIZE (1u << TBITS)           // 2,097,152 hash slots for ~1M keys
#define TMASK (TSIZE - 1u)
#define EMPTYK 0xFFFFFFFFu
#define MAXE 1050624
#define MAXN 40960
#define DUPCAP 262144

__device__ unsigned int g_hkey[TSIZE];
__device__ int          g_scnt[TSIZE];
__device__ int          g_dupid[TSIZE];
__device__ int          g_soe[MAXE];                       // slot of edge
__device__ __align__(16) float g_agg[MAXN * 64];           // node aggregation
__device__ __align__(16) float g_dupsum[(size_t)DUPCAP * 64];
__device__ int          g_ndup;

// ---------------- helpers ----------------
__device__ __forceinline__ unsigned int mixh(unsigned int x) {
    x ^= x >> 16; x *= 0x7feb352du;
    x ^= x >> 15; x *= 0x846ca68bu;
    x ^= x >> 16; return x;
}

__device__ __forceinline__ void red4(float* p, float4 v) {
    asm volatile("red.global.add.v4.f32 [%0], {%1,%2,%3,%4};"
                 :: "l"(p), "f"(v.x), "f"(v.y), "f"(v.z), "f"(v.w) : "memory");
}

__device__ __forceinline__ unsigned long long fma2(unsigned long long a,
                                                   unsigned long long b,
                                                   unsigned long long c) {
    unsigned long long d;
    asm("fma.rn.f32x2 %0, %1, %2, %3;" : "=l"(d) : "l"(a), "l"(b), "l"(c));
    return d;
}

__device__ __forceinline__ unsigned long long packdup(float x) {
    unsigned long long r;
    asm("mov.b64 %0, {%1, %1};" : "=l"(r) : "f"(x));
    return r;
}

__device__ __forceinline__ float2 unpk(unsigned long long a) {
    float2 v;
    asm("mov.b64 {%0, %1}, %2;" : "=f"(v.x), "=f"(v.y) : "l"(a));
    return v;
}

// ---------------- kernel 1: init ----------------
__global__ void k_init(int nagg4) {
    int idx = blockIdx.x * 256 + threadIdx.x;
    if (idx < nagg4) ((float4*)g_agg)[idx] = make_float4(0.f, 0.f, 0.f, 0.f);
    if (idx < (int)TSIZE) { g_hkey[idx] = EMPTYK; g_scnt[idx] = 0; }
    if (idx == 0) g_ndup = 0;
}

// ---------------- kernel 2: hash insert + count + node aggregation ----------------
__global__ __launch_bounds__(256) void k_insert(const float* __restrict__ ef,
                                                const int* __restrict__ esrc,
                                                const int* __restrict__ edst,
                                                int nn, int E) {
    int i = blockIdx.x * 256 + threadIdx.x;
    if (i >= E) return;
    int s = esrc[i], d = edst[i];
    unsigned int key = (unsigned int)s * (unsigned int)nn + (unsigned int)d;
    unsigned int h = mixh(key) & TMASK;
    for (;;) {
        unsigned int prev = atomicCAS(&g_hkey[h], EMPTYK, key);
        if (prev == EMPTYK || prev == key) break;
        h = (h + 1u) & TMASK;
    }
    g_soe[i] = (int)h;
    atomicAdd(&g_scnt[h], 1);

    const float4* row = (const float4*)(ef + (size_t)i * 64);
    float* ar = g_agg + (size_t)d * 64;
#pragma unroll
    for (int c = 0; c < 16; c++) {
        float4 v = row[c];
        red4(ar + 4 * c, v);
    }
}

// ---------------- kernel 3: assign dup ids (and zero their sums) ----------------
__global__ void k_dupassign() {
    int t = blockIdx.x * 256 + threadIdx.x;
    if (t >= (int)TSIZE) return;
    if (g_hkey[t] != EMPTYK && g_scnt[t] > 1) {
        int d = atomicAdd(&g_ndup, 1);
        if (d < DUPCAP) {
            g_dupid[t] = d;
            float4* p = (float4*)(g_dupsum + (size_t)d * 64);
#pragma unroll
            for (int c = 0; c < 16; c++) p[c] = make_float4(0.f, 0.f, 0.f, 0.f);
        } else {
            g_dupid[t] = -1;
        }
    } else {
        g_dupid[t] = -1;
    }
}

// ---------------- kernel 4: accumulate duplicated groups ----------------
__global__ __launch_bounds__(256) void k_dupacc(const float* __restrict__ ef, int E) {
    int i = blockIdx.x * 256 + threadIdx.x;
    if (i >= E) return;
    int s = g_soe[i];
    int d = g_dupid[s];
    if (d < 0) return;
    const float4* row = (const float4*)(ef + (size_t)i * 64);
    float* p = g_dupsum + (size_t)d * 64;
#pragma unroll
    for (int c = 0; c < 16; c++) {
        float4 v = row[c];
        red4(p + 4 * c, v);
    }
}

// ---------------- kernel 5: fused message + dense(relu) ----------------
__device__ __forceinline__ void fma_k(unsigned long long* acc, float hk,
                                      const float* Wrow) {
    unsigned long long h2 = packdup(hk);
    const ulonglong2* wp = (const ulonglong2*)Wrow;
#pragma unroll
    for (int j = 0; j < 16; j++) {
        ulonglong2 w = wp[j];
        acc[2 * j]     = fma2(h2, w.x, acc[2 * j]);
        acc[2 * j + 1] = fma2(h2, w.y, acc[2 * j + 1]);
    }
}

__global__ __launch_bounds__(256, 2) void k_fused(const float* __restrict__ ef,
                                                  const int* __restrict__ esrc,
                                                  const float* __restrict__ W,
                                                  const float* __restrict__ bias,
                                                  float* __restrict__ out, int E) {
    __shared__ __align__(16) float Wsh[128 * 64];
    for (int idx = threadIdx.x; idx < 128 * 64; idx += 256) Wsh[idx] = W[idx];
    __syncthreads();

    int i = blockIdx.x * 256 + threadIdx.x;
    if (i >= E) return;

    unsigned long long acc[32];
    const float2* b2 = (const float2*)bias;
#pragma unroll
    for (int p = 0; p < 32; p++) {
        float2 bv = __ldg(&b2[p]);
        asm("mov.b64 %0, {%1, %2};" : "=l"(acc[p]) : "f"(bv.x), "f"(bv.y));
    }

    // phase A: k = 0..63, h = edge_feature[i]
    const float4* efp = (const float4*)(ef + (size_t)i * 64);
#pragma unroll 4
    for (int c = 0; c < 16; c++) {
        float4 h4 = efp[c];
        fma_k(acc, h4.x, &Wsh[(4 * c + 0) * 64]);
        fma_k(acc, h4.y, &Wsh[(4 * c + 1) * 64]);
        fma_k(acc, h4.z, &Wsh[(4 * c + 2) * 64]);
        fma_k(acc, h4.w, &Wsh[(4 * c + 3) * 64]);
    }

    // phase B: k = 64..127, h = agg[src] - reverse_group_sum
    int src = esrc[i];
    int m = (i < E / 2) ? (i + E / 2) : (i - E / 2);   // mirror edge: key(m) == rev key(i)
    int sm = g_soe[m];
    int dp = (g_scnt[sm] > 1) ? g_dupid[sm] : -1;
    const float4* revp = (dp >= 0) ? (const float4*)(g_dupsum + (size_t)dp * 64)
                                   : (const float4*)(ef + (size_t)m * 64);
    const float4* aggp = (const float4*)(g_agg + (size_t)src * 64);
#pragma unroll 4
    for (int c = 0; c < 16; c++) {
        float4 a = aggp[c];
        float4 r = revp[c];
        float4 h4 = make_float4(a.x - r.x, a.y - r.y, a.z - r.z, a.w - r.w);
        fma_k(acc, h4.x, &Wsh[(64 + 4 * c + 0) * 64]);
        fma_k(acc, h4.y, &Wsh[(64 + 4 * c + 1) * 64]);
        fma_k(acc, h4.z, &Wsh[(64 + 4 * c + 2) * 64]);
        fma_k(acc, h4.w, &Wsh[(64 + 4 * c + 3) * 64]);
    }

    // relu + store
    float4* op = (float4*)(out + (size_t)i * 64);
#pragma unroll
    for (int j = 0; j < 16; j++) {
        float2 v0 = unpk(acc[2 * j]);
        float2 v1 = unpk(acc[2 * j + 1]);
        op[j] = make_float4(fmaxf(v0.x, 0.f), fmaxf(v0.y, 0.f),
                            fmaxf(v1.x, 0.f), fmaxf(v1.y, 0.f));
    }
}

// ---------------- launch ----------------
extern "C" void kernel_launch(void* const* d_in, const int* in_sizes, int n_in,
                              void* d_out, int out_size) {
    // metadata order: edge_feature, edge_src, edge_dst, graph_indicator, num_nodes, W, b
    const float* ef   = (const float*)d_in[0];
    const int*   esrc = (const int*)d_in[1];
    const int*   edst = (const int*)d_in[2];
    const float* W    = (const float*)d_in[5];
    const float* bias = (const float*)d_in[6];
    float* out = (float*)d_out;

    int E  = in_sizes[1];         // number of directed edges
    int nn = in_sizes[3];         // num_nodes == len(graph_indicator)

    int nagg4 = nn * 16;          // float4 count of agg
    int initN = nagg4 > (int)TSIZE ? nagg4 : (int)TSIZE;

    k_init<<<(initN + 255) / 256, 256>>>(nagg4);
    k_insert<<<(E + 255) / 256, 256>>>(ef, esrc, edst, nn, E);
    k_dupassign<<<((int)TSIZE + 255) / 256, 256>>>();
    k_dupacc<<<(E + 255) / 256, 256>>>(ef, E);
    k_fused<<<(E + 255) / 256, 256>>>(ef, esrc, W, bias, out, E);
}

// round 3
// speedup vs baseline: 2.2672x; 2.2672x over previous
#include <cuda_runtime.h>
#include <cuda_fp16.h>
#include <cstdint>

// ---------------- static scratch ----------------
#define TBITS 21
#define TSIZE (1u << TBITS)
#define TMASK (TSIZE - 1u)
#define EMPTYK 0xFFFFFFFFu
#define MAXE 1050624
#define MAXN 40960
#define DUPCAP 262144

__device__ unsigned int  g_hkey[TSIZE];
__device__ unsigned char g_dupflag[TSIZE];
__device__ int           g_dupid[TSIZE];
__device__ int           g_soe[MAXE];
__device__ __align__(16) float g_agg[MAXN * 64];
__device__ __align__(16) float g_dupsum[(size_t)DUPCAP * 64];
__device__ int           g_ndup;

// ---------------- helpers ----------------
__device__ __forceinline__ unsigned int mixh(unsigned int x) {
    x ^= x >> 16; x *= 0x7feb352du;
    x ^= x >> 15; x *= 0x846ca68bu;
    x ^= x >> 16; return x;
}

__device__ __forceinline__ void red4(float* p, float4 v) {
    asm volatile("red.global.add.v4.f32 [%0], {%1,%2,%3,%4};"
                 :: "l"(p), "f"(v.x), "f"(v.y), "f"(v.z), "f"(v.w) : "memory");
}

// fp16 split: x -> hi(f16x2) + lo(f16x2 of residual); elem .x in low half
__device__ __forceinline__ void cvt_split(float2 x, uint32_t& hi, uint32_t& lo) {
    __half2 h = __float22half2_rn(x);
    float2 hb = __half22float2(h);
    __half2 l = __floats2half2_rn(x.x - hb.x, x.y - hb.y);
    hi = *(uint32_t*)&h;
    lo = *(uint32_t*)&l;
}

__device__ __forceinline__ void mma16816(float* c, const uint32_t* a,
                                         uint32_t b0, uint32_t b1) {
    asm("mma.sync.aligned.m16n8k16.row.col.f32.f16.f16.f32 "
        "{%0,%1,%2,%3}, {%4,%5,%6,%7}, {%8,%9}, {%0,%1,%2,%3};"
        : "+f"(c[0]), "+f"(c[1]), "+f"(c[2]), "+f"(c[3])
        : "r"(a[0]), "r"(a[1]), "r"(a[2]), "r"(a[3]), "r"(b0), "r"(b1));
}

// ---------------- kernel: hash insert + node aggregation ----------------
__global__ __launch_bounds__(256) void k_insert(const float* __restrict__ ef,
                                                const int* __restrict__ esrc,
                                                const int* __restrict__ edst,
                                                int nn, int E) {
    int i = blockIdx.x * 256 + threadIdx.x;
    if (i >= E) return;
    int s = esrc[i], d = edst[i];
    unsigned int key = (unsigned int)s * (unsigned int)nn + (unsigned int)d;
    unsigned int h = mixh(key) & TMASK;
    for (;;) {
        unsigned int prev = atomicCAS(&g_hkey[h], EMPTYK, key);
        if (prev == EMPTYK) break;
        if (prev == key) { g_dupflag[h] = 1; break; }
        h = (h + 1u) & TMASK;
    }
    g_soe[i] = (int)h;

    const float4* row = (const float4*)(ef + (size_t)i * 64);
    float* ar = g_agg + (size_t)d * 64;
#pragma unroll
    for (int c = 0; c < 16; c++) red4(ar + 4 * c, row[c]);
}

// ---------------- kernel: assign dup ids ----------------
__global__ void k_dupassign() {
    int t = blockIdx.x * 256 + threadIdx.x;
    if (t >= (int)TSIZE) return;
    if (g_dupflag[t]) {
        int d = atomicAdd(&g_ndup, 1);
        if (d < DUPCAP) {
            g_dupid[t] = d;
            float4* p = (float4*)(g_dupsum + (size_t)d * 64);
#pragma unroll
            for (int c = 0; c < 16; c++) p[c] = make_float4(0.f, 0.f, 0.f, 0.f);
        } else g_dupid[t] = -1;
    } else {
        g_dupid[t] = -1;
    }
}

// ---------------- kernel: accumulate duplicated groups ----------------
__global__ __launch_bounds__(256) void k_dupacc(const float* __restrict__ ef, int E) {
    int i = blockIdx.x * 256 + threadIdx.x;
    if (i >= E) return;
    int d = g_dupid[g_soe[i]];
    if (d < 0) return;
    const float4* row = (const float4*)(ef + (size_t)i * 64);
    float* p = g_dupsum + (size_t)d * 64;
#pragma unroll
    for (int c = 0; c < 16; c++) red4(p + 4 * c, row[c]);
}

// ---------------- fused: message + HMMA GEMM + bias + relu ----------------
// Per warp: M=32 edges x N=64, K=128 (h = [ef | agg[src]-rev]).
// A fragments generated directly from gmem (no staging); W fragments in SMEM.
// 3-product fp16 split: xh*wh + xl*wh + xh*wl.
__global__ __launch_bounds__(256, 2) void k_fused_mma(const float* __restrict__ ef,
                                                      const int* __restrict__ esrc,
                                                      const float* __restrict__ W,
                                                      const float* __restrict__ bias,
                                                      float* __restrict__ out, int E) {
    __shared__ uint2 Bf[2][8][8][32];   // [split][kb][nb][lane] = (b0,b1)  32KB

    const int tid  = threadIdx.x;
    const int lane = tid & 31;
    const int wid  = tid >> 5;
    const int q    = lane & 3;     // k-pair selector within fragment
    const int g    = lane >> 2;    // row-in-group

    // Build W fragments (hi & lo splits) in the exact mma B register layout.
    for (int idx = tid; idx < 4096; idx += 256) {
        int split = idx >> 11, kb = (idx >> 8) & 7, nb = (idx >> 5) & 7, L = idx & 31;
        int qq = L & 3, n = nb * 8 + (L >> 2);
        int k0 = kb * 16 + 2 * qq;
        float w00 = W[k0 * 64 + n],       w01 = W[(k0 + 1) * 64 + n];
        float w10 = W[(k0 + 8) * 64 + n], w11 = W[(k0 + 9) * 64 + n];
        uint32_t h0, l0, h1, l1;
        cvt_split(make_float2(w00, w01), h0, l0);
        cvt_split(make_float2(w10, w11), h1, l1);
        Bf[split][kb][nb][L] = (split == 0) ? make_uint2(h0, h1) : make_uint2(l0, l1);
    }
    __syncthreads();

    const int E2 = E >> 1;
    const int nwt = (E + 31) >> 5;

    for (int wt = blockIdx.x * 8 + wid; wt < nwt; wt += gridDim.x * 8) {
        const int e0 = wt * 32;

        const float2* efp[4];
        const float2* srcp[4];
        const float2* revp[4];
        bool val[4];
#pragma unroll
        for (int j = 0; j < 4; j++) {
            int e = e0 + g + 8 * j;
            val[j] = e < E;
            int ec = val[j] ? e : E - 1;
            efp[j]  = (const float2*)(ef + (size_t)ec * 64);
            srcp[j] = (const float2*)(g_agg + (size_t)__ldg(&esrc[ec]) * 64);
            int mm = (ec < E2) ? (ec + E2) : (ec - E2);
            int dp = g_dupid[g_soe[mm]];
            revp[j] = (dp >= 0) ? (const float2*)(g_dupsum + (size_t)dp * 64)
                                : (const float2*)(ef + (size_t)mm * 64);
        }

        float acc[2][8][4];
#pragma unroll
        for (int mb = 0; mb < 2; mb++)
#pragma unroll
            for (int nb = 0; nb < 8; nb++)
#pragma unroll
                for (int c = 0; c < 4; c++) acc[mb][nb][c] = 0.f;

#pragma unroll
        for (int kb = 0; kb < 8; kb++) {
            uint32_t ah[2][4], al[2][4];
#pragma unroll
            for (int mb = 0; mb < 2; mb++) {
#pragma unroll
                for (int j2 = 0; j2 < 2; j2++) {
                    int j = mb * 2 + j2;
                    float2 x0, x1;
                    if (kb < 4) {
                        x0 = efp[j][kb * 8 + q];
                        x1 = efp[j][kb * 8 + q + 4];
                    } else {
                        int kk = kb - 4;
                        float2 a0 = srcp[j][kk * 8 + q];
                        float2 r0 = revp[j][kk * 8 + q];
                        float2 a1 = srcp[j][kk * 8 + q + 4];
                        float2 r1 = revp[j][kk * 8 + q + 4];
                        x0 = make_float2(a0.x - r0.x, a0.y - r0.y);
                        x1 = make_float2(a1.x - r1.x, a1.y - r1.y);
                    }
                    cvt_split(x0, ah[mb][0 + j2], al[mb][0 + j2]);
                    cvt_split(x1, ah[mb][2 + j2], al[mb][2 + j2]);
                }
            }
#pragma unroll
            for (int nb = 0; nb < 8; nb++) {
                uint2 bh = Bf[0][kb][nb][lane];
                uint2 bl = Bf[1][kb][nb][lane];
#pragma unroll
                for (int mb = 0; mb < 2; mb++) {
                    mma16816(acc[mb][nb], ah[mb], bh.x, bh.y);   // xh*wh
                    mma16816(acc[mb][nb], al[mb], bh.x, bh.y);   // xl*wh
                    mma16816(acc[mb][nb], ah[mb], bl.x, bl.y);   // xh*wl
                }
            }
        }

        // epilogue: bias + relu, direct coalesced-sector stores
#pragma unroll
        for (int mb = 0; mb < 2; mb++) {
#pragma unroll
            for (int nb = 0; nb < 8; nb++) {
                int col = nb * 8 + 2 * q;
                float2 bv = __ldg((const float2*)(bias + col));
                if (val[mb * 2]) {
                    float2 o = make_float2(fmaxf(acc[mb][nb][0] + bv.x, 0.f),
                                           fmaxf(acc[mb][nb][1] + bv.y, 0.f));
                    *(float2*)(out + (size_t)(e0 + mb * 16 + g) * 64 + col) = o;
                }
                if (val[mb * 2 + 1]) {
                    float2 o = make_float2(fmaxf(acc[mb][nb][2] + bv.x, 0.f),
                                           fmaxf(acc[mb][nb][3] + bv.y, 0.f));
                    *(float2*)(out + (size_t)(e0 + mb * 16 + g + 8) * 64 + col) = o;
                }
            }
        }
    }
}

// ---------------- launch ----------------
extern "C" void kernel_launch(void* const* d_in, const int* in_sizes, int n_in,
                              void* d_out, int out_size) {
    const float* ef   = (const float*)d_in[0];
    const int*   esrc = (const int*)d_in[1];
    const int*   edst = (const int*)d_in[2];
    const float* W    = (const float*)d_in[5];
    const float* bias = (const float*)d_in[6];
    float* out = (float*)d_out;

    int E  = in_sizes[1];
    int nn = in_sizes[3];

    void *p_hkey, *p_flag, *p_agg, *p_ndup;
    cudaGetSymbolAddress(&p_hkey, g_hkey);
    cudaGetSymbolAddress(&p_flag, g_dupflag);
    cudaGetSymbolAddress(&p_agg,  g_agg);
    cudaGetSymbolAddress(&p_ndup, g_ndup);

    cudaMemsetAsync(p_hkey, 0xFF, (size_t)TSIZE * 4);
    cudaMemsetAsync(p_flag, 0x00, (size_t)TSIZE);
    cudaMemsetAsync(p_agg,  0x00, (size_t)nn * 64 * 4);
    cudaMemsetAsync(p_ndup, 0x00, 4);

    k_insert<<<(E + 255) / 256, 256>>>(ef, esrc, edst, nn, E);
    k_dupassign<<<((int)TSIZE + 255) / 256, 256>>>();
    k_dupacc<<<(E + 255) / 256, 256>>>(ef, E);

    k_fused_mma<<<296, 256>>>(ef, esrc, W, bias, out, E);
}